// round 2
// baseline (speedup 1.0000x reference)
#include <cuda_runtime.h>
#include <cuda_bf16.h>
#include <math.h>

// Problem constants
#define NB   64     // batch
#define TT   512    // time steps
#define DD   512    // input dim
#define HH   512    // hidden dim
#define G4   2048   // 4*H

// ---------------------------------------------------------------------------
// Scratch (device globals: the sanctioned no-alloc workaround)
// ---------------------------------------------------------------------------
__device__ float    g_xh[(size_t)TT * NB * G4];   // (T, N, 4H) pre-projected gates, biases folded
__device__ unsigned g_bar[TT];                    // per-step grid barrier counters

// ---------------------------------------------------------------------------
// Kernel 1: xh = x @ W_xh + (b_xh + b_hh)
// A rows are gathered: row m = t*64+n -> x[n][t][:]
// 128x128x8 tile, 256 threads, warp-tiled 32x64, 8x8 per thread.
// ---------------------------------------------------------------------------
#define BM 128
#define BN 128
#define BK 8

__global__ __launch_bounds__(256)
void gemm_xh_kernel(const float* __restrict__ x,
                    const float* __restrict__ Wxh,
                    const float* __restrict__ bxh,
                    const float* __restrict__ bhh)
{
    __shared__ float As[BK][BM];   // transposed A tile
    __shared__ float Bs[BK][BN];

    const int tid = threadIdx.x;
    const int bm  = blockIdx.y;
    const int bn  = blockIdx.x;

    // warp tiling: 8 warps = 4 (m) x 2 (n); lane = 4 (m) x 8 (n)
    const int warp = tid >> 5, lane = tid & 31;
    const int wm = warp >> 1, wn = warp & 1;
    const int tm = lane & 3,  tn = lane >> 2;
    const int m0 = wm * 32 + tm * 8;
    const int n0 = wn * 64 + tn * 8;

    // A load mapping: row r = tid>>1, float4 quarter q = tid&1
    const int ar = tid >> 1;
    const int aq = tid & 1;
    const int gm = bm * BM + ar;            // global row m = t*64+n
    const int t  = gm >> 6;
    const int nn = gm & 63;
    const float* __restrict__ arow = x + ((size_t)nn * TT + t) * DD;

    // B load mapping: row rb = tid>>5 (0..7), col cb = (tid&31)*4
    const int rb = tid >> 5;
    const int cb = (tid & 31) * 4;
    const float* __restrict__ bcol = Wxh + (size_t)bn * BN + cb;

    float acc[8][8];
#pragma unroll
    for (int i = 0; i < 8; i++)
#pragma unroll
        for (int j = 0; j < 8; j++) acc[i][j] = 0.f;

    for (int k0 = 0; k0 < DD; k0 += BK) {
        const float4 av = *(const float4*)(arow + k0 + aq * 4);
        const float4 bv = *(const float4*)(bcol + (size_t)(k0 + rb) * G4);
        __syncthreads();   // previous iter's smem reads done
        As[aq * 4 + 0][ar] = av.x;
        As[aq * 4 + 1][ar] = av.y;
        As[aq * 4 + 2][ar] = av.z;
        As[aq * 4 + 3][ar] = av.w;
        *(float4*)&Bs[rb][cb] = bv;
        __syncthreads();

#pragma unroll
        for (int kk = 0; kk < BK; kk++) {
            float ra[8], rv[8];
            *(float4*)&ra[0] = *(const float4*)&As[kk][m0];
            *(float4*)&ra[4] = *(const float4*)&As[kk][m0 + 4];
            *(float4*)&rv[0] = *(const float4*)&Bs[kk][n0];
            *(float4*)&rv[4] = *(const float4*)&Bs[kk][n0 + 4];
#pragma unroll
            for (int i = 0; i < 8; i++)
#pragma unroll
                for (int j = 0; j < 8; j++)
                    acc[i][j] = fmaf(ra[i], rv[j], acc[i][j]);
        }
    }

    // epilogue: add both biases, write g_xh
    const int col0 = bn * BN + n0;
    float4 b0, b1;
    {
        const float4 x0 = *(const float4*)(bxh + col0);
        const float4 x1 = *(const float4*)(bxh + col0 + 4);
        const float4 h0 = *(const float4*)(bhh + col0);
        const float4 h1 = *(const float4*)(bhh + col0 + 4);
        b0 = make_float4(x0.x + h0.x, x0.y + h0.y, x0.z + h0.z, x0.w + h0.w);
        b1 = make_float4(x1.x + h1.x, x1.y + h1.y, x1.z + h1.z, x1.w + h1.w);
    }
#pragma unroll
    for (int i = 0; i < 8; i++) {
        const size_t row = (size_t)(bm * BM + m0 + i);
        float* p = g_xh + row * G4 + col0;
        float4 v0 = make_float4(acc[i][0] + b0.x, acc[i][1] + b0.y,
                                acc[i][2] + b0.z, acc[i][3] + b0.w);
        float4 v1 = make_float4(acc[i][4] + b1.x, acc[i][5] + b1.y,
                                acc[i][6] + b1.z, acc[i][7] + b1.w);
        *(float4*)p       = v0;
        *(float4*)(p + 4) = v1;
    }
}

// ---------------------------------------------------------------------------
// Kernel 2: barrier counter reset (runs each launch before the LSTM kernel,
// keeping graph replays deterministic)
// ---------------------------------------------------------------------------
__global__ void reset_bar_kernel()
{
    if (threadIdx.x < TT) g_bar[threadIdx.x] = 0u;
}

// ---------------------------------------------------------------------------
// Kernel 3: persistent LSTM recurrence.
// 128 CTAs x 256 threads. CTA b owns hidden cols [b*4, b*4+4).
// W_hh slice (512 x 16) stays in smem for the whole kernel.
// Thread (n = tid>>2, cg = tid&3) computes gate-type cg for 4 cols of batch n.
// h state lives in d_out (y); c state lives in registers.
// Grid barrier per step: red.release.gpu + ld.acquire.gpu spin (CG pattern).
// ---------------------------------------------------------------------------
#define NCTA 128
#define CPC  4      // hidden cols per CTA

__device__ __forceinline__ float sigmoidf_(float v)
{
    return 1.f / (1.f + expf(-v));
}

__global__ __launch_bounds__(256, 1)
void lstm_kernel(const float* __restrict__ Whh, float* __restrict__ y)
{
    __shared__ float4 ws4[HH * 4];      // [k][cg] -> Whh[k][cg*512 + jh0 .. +3]; 32 KB
    __shared__ float  gs[NB][17];       // gate staging, padded

    const int tid = threadIdx.x;
    const int b   = blockIdx.x;
    const int jh0 = b * CPC;
    const int n   = tid >> 2;           // 0..63
    const int cg  = tid & 3;            // gate type: 0=i 1=f 2=g 3=o

    // load W_hh slice into smem once
    for (int i = tid; i < HH * 4; i += 256) {
        const int k = i >> 2, g = i & 3;
        ws4[i] = *(const float4*)(Whh + (size_t)k * G4 + (size_t)g * HH + jh0);
    }
    __syncthreads();

    // activation-phase mapping: thread -> one (n2, j2) output column
    const int n2 = tid >> 2;
    const int j2 = tid & 3;
    float creg = 0.f;                   // c state for (n2, jh0+j2)

    const float* __restrict__ hbase = y + (size_t)n * TT * HH;

    for (int tstep = 0; tstep < TT; tstep++) {
        float a0 = 0.f, a1 = 0.f, a2 = 0.f, a3 = 0.f;

        if (tstep > 0) {
            const float* __restrict__ hrow = hbase + (size_t)(tstep - 1) * HH;
#pragma unroll 8
            for (int k = 0; k < HH; k += 4) {
                const float4 hv = *(const float4*)(hrow + k);
                const float4 w0 = ws4[(k + 0) * 4 + cg];
                const float4 w1 = ws4[(k + 1) * 4 + cg];
                const float4 w2 = ws4[(k + 2) * 4 + cg];
                const float4 w3 = ws4[(k + 3) * 4 + cg];
                a0 = fmaf(hv.x, w0.x, a0); a1 = fmaf(hv.x, w0.y, a1);
                a2 = fmaf(hv.x, w0.z, a2); a3 = fmaf(hv.x, w0.w, a3);
                a0 = fmaf(hv.y, w1.x, a0); a1 = fmaf(hv.y, w1.y, a1);
                a2 = fmaf(hv.y, w1.z, a2); a3 = fmaf(hv.y, w1.w, a3);
                a0 = fmaf(hv.z, w2.x, a0); a1 = fmaf(hv.z, w2.y, a1);
                a2 = fmaf(hv.z, w2.z, a2); a3 = fmaf(hv.z, w2.w, a3);
                a0 = fmaf(hv.w, w3.x, a0); a1 = fmaf(hv.w, w3.y, a1);
                a2 = fmaf(hv.w, w3.z, a2); a3 = fmaf(hv.w, w3.w, a3);
            }
        }

        // add pre-projected input gates (biases already folded in)
        {
            const float4 xv = *(const float4*)(g_xh +
                ((size_t)tstep * NB + n) * G4 + (size_t)cg * HH + jh0);
            a0 += xv.x; a1 += xv.y; a2 += xv.z; a3 += xv.w;
        }

        gs[n][cg * 4 + 0] = a0;
        gs[n][cg * 4 + 1] = a1;
        gs[n][cg * 4 + 2] = a2;
        gs[n][cg * 4 + 3] = a3;
        __syncthreads();

        // activations: one output column per thread
        {
            const float gi = gs[n2][0  + j2];
            const float gf = gs[n2][4  + j2];
            const float gc = gs[n2][8  + j2];
            const float go = gs[n2][12 + j2];
            const float iv = sigmoidf_(gi);
            const float fv = sigmoidf_(gf);
            const float gv = tanhf(gc);
            const float ov = sigmoidf_(go);
            creg = fv * creg + iv * gv;
            const float hv = ov * tanhf(creg);
            y[(size_t)n2 * TT * HH + (size_t)tstep * HH + jh0 + j2] = hv;
        }
        __syncthreads();   // gs reusable; all y stores program-ordered before barrier

        if (tstep < TT - 1) {
            // grid barrier (release/acquire, same pattern as CG grid.sync)
            if (tid == 0) {
                unsigned* ctr = &g_bar[tstep];
                asm volatile("red.release.gpu.add.u32 [%0], %1;"
                             :: "l"(ctr), "r"(1u) : "memory");
                unsigned v;
                do {
                    asm volatile("ld.acquire.gpu.u32 %0, [%1];"
                                 : "=r"(v) : "l"(ctr) : "memory");
                } while (v < (unsigned)NCTA);
            }
            __syncthreads();
        }
    }
}

// ---------------------------------------------------------------------------
// Launch
// ---------------------------------------------------------------------------
extern "C" void kernel_launch(void* const* d_in, const int* in_sizes, int n_in,
                              void* d_out, int out_size)
{
    const float* x   = (const float*)d_in[0];   // (64, 512, 512)
    const float* Wxh = (const float*)d_in[1];   // (512, 2048)
    const float* Whh = (const float*)d_in[2];   // (512, 2048)
    const float* bxh = (const float*)d_in[3];   // (2048,)
    const float* bhh = (const float*)d_in[4];   // (2048,)
    float* y = (float*)d_out;                   // (64, 512, 512)

    // barrier reset must precede the persistent kernel each call (graph replays)
    reset_bar_kernel<<<1, TT>>>();

    dim3 ggrid(G4 / BN, (TT * NB) / BM);        // (16, 256)
    gemm_xh_kernel<<<ggrid, 256>>>(x, Wxh, bxh, bhh);

    lstm_kernel<<<NCTA, 256>>>(Whh, y);
}

// round 3
// speedup vs baseline: 1.0146x; 1.0146x over previous
#include <cuda_runtime.h>
#include <cuda_bf16.h>
#include <math.h>

// Problem constants
#define NB   64     // batch
#define TT   512    // time steps
#define DD   512    // input dim
#define HH   512    // hidden dim
#define G4   2048   // 4*H

typedef unsigned long long u64;

// ---------------------------------------------------------------------------
// Packed f32x2 helpers (sm_103a FFMA2 — ptxas never auto-generates these)
// ---------------------------------------------------------------------------
__device__ __forceinline__ u64 pack_dup(float v)
{
    u64 r; asm("mov.b64 %0, {%1, %1};" : "=l"(r) : "f"(v)); return r;
}
__device__ __forceinline__ void ffma2(u64& acc, u64 a, u64 b)
{
    asm("fma.rn.f32x2 %0, %1, %2, %0;" : "+l"(acc) : "l"(a), "l"(b));
}
__device__ __forceinline__ float2 unpk(u64 v)
{
    float2 r; asm("mov.b64 {%0, %1}, %2;" : "=f"(r.x), "=f"(r.y) : "l"(v)); return r;
}

// ---------------------------------------------------------------------------
// Scratch (device globals: the sanctioned no-alloc workaround)
// ---------------------------------------------------------------------------
__device__ float    g_xh[(size_t)TT * NB * G4];   // (T, N, 4H) pre-projected gates, biases folded
__device__ unsigned g_bar[TT];                    // per-step grid barrier counters

// ---------------------------------------------------------------------------
// Kernel 1: xh = x @ W_xh + (b_xh + b_hh)   — FFMA2 inner loop
// 128x128x8 tile, 256 threads, warp-tiled 32x64, 8x8 per thread.
// Accumulators are packed f32x2 over adjacent n-columns.
// ---------------------------------------------------------------------------
#define BM 128
#define BN 128
#define BK 8

__global__ __launch_bounds__(256, 2)
void gemm_xh_kernel(const float* __restrict__ x,
                    const float* __restrict__ Wxh,
                    const float* __restrict__ bxh,
                    const float* __restrict__ bhh)
{
    __shared__ float As[BK][BM];   // transposed A tile
    __shared__ float Bs[BK][BN];

    const int tid = threadIdx.x;
    const int bm  = blockIdx.y;
    const int bn  = blockIdx.x;

    // warp tiling: 8 warps = 4 (m) x 2 (n); lane = 4 (m) x 8 (n)
    const int warp = tid >> 5, lane = tid & 31;
    const int wm = warp >> 1, wn = warp & 1;
    const int tm = lane & 3,  tn = lane >> 2;
    const int m0 = wm * 32 + tm * 8;
    const int n0 = wn * 64 + tn * 8;

    // A load mapping: row r = tid>>1, float4 quarter q = tid&1
    const int ar = tid >> 1;
    const int aq = tid & 1;
    const int gm = bm * BM + ar;            // global row m = t*64+n
    const int t  = gm >> 6;
    const int nn = gm & 63;
    const float* __restrict__ arow = x + ((size_t)nn * TT + t) * DD;

    // B load mapping: row rb = tid>>5 (0..7), col cb = (tid&31)*4
    const int rb = tid >> 5;
    const int cb = (tid & 31) * 4;
    const float* __restrict__ bcol = Wxh + (size_t)bn * BN + cb;

    u64 acc2[8][4];                 // [i][jp] packed pair over columns (2*jp, 2*jp+1)
#pragma unroll
    for (int i = 0; i < 8; i++)
#pragma unroll
        for (int j = 0; j < 4; j++) acc2[i][j] = 0ull;

    for (int k0 = 0; k0 < DD; k0 += BK) {
        const float4 av = *(const float4*)(arow + k0 + aq * 4);
        const float4 bv = *(const float4*)(bcol + (size_t)(k0 + rb) * G4);
        __syncthreads();   // previous iter's smem reads done
        As[aq * 4 + 0][ar] = av.x;
        As[aq * 4 + 1][ar] = av.y;
        As[aq * 4 + 2][ar] = av.z;
        As[aq * 4 + 3][ar] = av.w;
        *(float4*)&Bs[rb][cb] = bv;
        __syncthreads();

#pragma unroll
        for (int kk = 0; kk < BK; kk++) {
            float ra[8];
            *(float4*)&ra[0] = *(const float4*)&As[kk][m0];
            *(float4*)&ra[4] = *(const float4*)&As[kk][m0 + 4];
            const ulonglong2 b01 = *(const ulonglong2*)&Bs[kk][n0];
            const ulonglong2 b23 = *(const ulonglong2*)&Bs[kk][n0 + 4];
#pragma unroll
            for (int i = 0; i < 8; i++) {
                const u64 ai = pack_dup(ra[i]);
                ffma2(acc2[i][0], ai, b01.x);
                ffma2(acc2[i][1], ai, b01.y);
                ffma2(acc2[i][2], ai, b23.x);
                ffma2(acc2[i][3], ai, b23.y);
            }
        }
    }

    // epilogue: add both biases, write g_xh
    const int col0 = bn * BN + n0;
    float bsum[8];
#pragma unroll
    for (int j = 0; j < 8; j++)
        bsum[j] = bxh[col0 + j] + bhh[col0 + j];

#pragma unroll
    for (int i = 0; i < 8; i++) {
        const size_t row = (size_t)(bm * BM + m0 + i);
        float* p = g_xh + row * G4 + col0;
        float2 c0 = unpk(acc2[i][0]);
        float2 c1 = unpk(acc2[i][1]);
        float2 c2 = unpk(acc2[i][2]);
        float2 c3 = unpk(acc2[i][3]);
        float4 v0 = make_float4(c0.x + bsum[0], c0.y + bsum[1],
                                c1.x + bsum[2], c1.y + bsum[3]);
        float4 v1 = make_float4(c2.x + bsum[4], c2.y + bsum[5],
                                c3.x + bsum[6], c3.y + bsum[7]);
        *(float4*)p       = v0;
        *(float4*)(p + 4) = v1;
    }
}

// ---------------------------------------------------------------------------
// Kernel 2: barrier counter reset (runs each launch before the LSTM kernel,
// keeping graph replays deterministic)
// ---------------------------------------------------------------------------
__global__ void reset_bar_kernel()
{
    if (threadIdx.x < TT) g_bar[threadIdx.x] = 0u;
}

// ---------------------------------------------------------------------------
// Kernel 3: persistent LSTM recurrence — FFMA2 inner loop, zero packing.
// 128 CTAs x 256 threads. CTA b owns hidden cols [b*4, b*4+4).
// W_hh slice stored k-CONTIGUOUS per output column:
//   wsT[cg][j][k] = Whh[k][cg*512 + jh0 + j]
// so both FFMA2 operands arrive as natural 64-bit pairs:
//   {h[k],h[k+1]} from LDG.128, {w[k][j],w[k+1][j]} from LDS.128.
// cg slices padded (stride 2052 floats = 4-bank shift) -> conflict-free
// 4-address broadcast LDS.
// Thread (n = tid>>2, cg = tid&3) computes gate-type cg for 4 cols of batch n.
// h state lives in d_out (y); c state lives in registers.
// Grid barrier per step: red.release.gpu + ld.acquire.gpu spin.
// ---------------------------------------------------------------------------
#define NCTA 128
#define CPC  4            // hidden cols per CTA
#define WS_STRIDE 2052    // 4*512 + 4 floats per cg slice (bank-shift pad)

__device__ __forceinline__ float sigmoidf_(float v)
{
    return 1.f / (1.f + expf(-v));
}

__global__ __launch_bounds__(256, 1)
void lstm_kernel(const float* __restrict__ Whh, float* __restrict__ y)
{
    __shared__ float wsT[4 * WS_STRIDE];   // ~32.8 KB
    __shared__ float gs[NB][17];           // gate staging, padded

    const int tid = threadIdx.x;
    const int b   = blockIdx.x;
    const int jh0 = b * CPC;
    const int n   = tid >> 2;             // 0..63
    const int cg  = tid & 3;              // gate type: 0=i 1=f 2=g 3=o

    // load + transpose W_hh slice into smem once (one-time cost)
    for (int i = tid; i < 4 * 4 * HH; i += 256) {
        const int k = i & (HH - 1);
        const int j = (i >> 9) & 3;
        const int g = i >> 11;
        wsT[g * WS_STRIDE + j * HH + k] =
            Whh[(size_t)k * G4 + (size_t)g * HH + jh0 + j];
    }
    __syncthreads();

    const float* __restrict__ wbase = &wsT[cg * WS_STRIDE];

    // activation-phase mapping: thread -> one (n2, j2) output column
    const int n2 = tid >> 2;
    const int j2 = tid & 3;
    float creg = 0.f;                     // c state for (n2, jh0+j2)

    const float* __restrict__ hbase = y + (size_t)n * TT * HH;

    for (int tstep = 0; tstep < TT; tstep++) {
        u64 acc0 = 0ull, acc1 = 0ull, acc2v = 0ull, acc3 = 0ull;

        if (tstep > 0) {
            const float* __restrict__ hrow = hbase + (size_t)(tstep - 1) * HH;
#pragma unroll 8
            for (int k = 0; k < HH; k += 4) {
                const ulonglong2 hp = *(const ulonglong2*)(hrow + k);
                const ulonglong2 w0 = *(const ulonglong2*)(wbase + 0 * HH + k);
                const ulonglong2 w1 = *(const ulonglong2*)(wbase + 1 * HH + k);
                const ulonglong2 w2 = *(const ulonglong2*)(wbase + 2 * HH + k);
                const ulonglong2 w3 = *(const ulonglong2*)(wbase + 3 * HH + k);
                ffma2(acc0, hp.x, w0.x); ffma2(acc0, hp.y, w0.y);
                ffma2(acc1, hp.x, w1.x); ffma2(acc1, hp.y, w1.y);
                ffma2(acc2v, hp.x, w2.x); ffma2(acc2v, hp.y, w2.y);
                ffma2(acc3, hp.x, w3.x); ffma2(acc3, hp.y, w3.y);
            }
        }

        // horizontal reduce + pre-projected input gates (biases folded in)
        float a0, a1, a2, a3;
        {
            const float2 s0 = unpk(acc0), s1 = unpk(acc1);
            const float2 s2 = unpk(acc2v), s3 = unpk(acc3);
            const float4 xv = *(const float4*)(g_xh +
                ((size_t)tstep * NB + n) * G4 + (size_t)cg * HH + jh0);
            a0 = s0.x + s0.y + xv.x;
            a1 = s1.x + s1.y + xv.y;
            a2 = s2.x + s2.y + xv.z;
            a3 = s3.x + s3.y + xv.w;
        }

        gs[n][cg * 4 + 0] = a0;
        gs[n][cg * 4 + 1] = a1;
        gs[n][cg * 4 + 2] = a2;
        gs[n][cg * 4 + 3] = a3;
        __syncthreads();

        // activations: one output column per thread
        {
            const float gi = gs[n2][0  + j2];
            const float gf = gs[n2][4  + j2];
            const float gc = gs[n2][8  + j2];
            const float go = gs[n2][12 + j2];
            const float iv = sigmoidf_(gi);
            const float fv = sigmoidf_(gf);
            const float gv = tanhf(gc);
            const float ov = sigmoidf_(go);
            creg = fv * creg + iv * gv;
            const float hv = ov * tanhf(creg);
            y[(size_t)n2 * TT * HH + (size_t)tstep * HH + jh0 + j2] = hv;
        }
        __syncthreads();   // gs reusable; all y stores program-ordered before barrier

        if (tstep < TT - 1) {
            // grid barrier (release/acquire, same pattern as CG grid.sync)
            if (tid == 0) {
                unsigned* ctr = &g_bar[tstep];
                asm volatile("red.release.gpu.add.u32 [%0], %1;"
                             :: "l"(ctr), "r"(1u) : "memory");
                unsigned v;
                do {
                    asm volatile("ld.acquire.gpu.u32 %0, [%1];"
                                 : "=r"(v) : "l"(ctr) : "memory");
                } while (v < (unsigned)NCTA);
            }
            __syncthreads();
        }
    }
}

// ---------------------------------------------------------------------------
// Launch
// ---------------------------------------------------------------------------
extern "C" void kernel_launch(void* const* d_in, const int* in_sizes, int n_in,
                              void* d_out, int out_size)
{
    const float* x   = (const float*)d_in[0];   // (64, 512, 512)
    const float* Wxh = (const float*)d_in[1];   // (512, 2048)
    const float* Whh = (const float*)d_in[2];   // (512, 2048)
    const float* bxh = (const float*)d_in[3];   // (2048,)
    const float* bhh = (const float*)d_in[4];   // (2048,)
    float* y = (float*)d_out;                   // (64, 512, 512)

    // barrier reset must precede the persistent kernel each call (graph replays)
    reset_bar_kernel<<<1, TT>>>();

    dim3 ggrid(G4 / BN, (TT * NB) / BM);        // (16, 256)
    gemm_xh_kernel<<<ggrid, 256>>>(x, Wxh, bxh, bhh);

    lstm_kernel<<<NCTA, 256>>>(Whh, y);
}

// round 5
// speedup vs baseline: 1.1455x; 1.1290x over previous
#include <cuda_runtime.h>
#include <cuda_bf16.h>
#include <math.h>

// Problem constants
#define NB   64     // batch
#define TT   512    // time steps
#define DD   512    // input dim
#define HH   512    // hidden dim
#define G4   2048   // 4*H

typedef unsigned long long u64;

// ---------------------------------------------------------------------------
// Packed f32x2 helpers (sm_103a FFMA2 — ptxas never auto-generates these)
// ---------------------------------------------------------------------------
__device__ __forceinline__ u64 pack_dup(float v)
{
    u64 r; asm("mov.b64 %0, {%1, %1};" : "=l"(r) : "f"(v)); return r;
}
__device__ __forceinline__ void ffma2(u64& acc, u64 a, u64 b)
{
    asm("fma.rn.f32x2 %0, %1, %2, %0;" : "+l"(acc) : "l"(a), "l"(b));
}
__device__ __forceinline__ float2 unpk(u64 v)
{
    float2 r; asm("mov.b64 {%0, %1}, %2;" : "=f"(r.x), "=f"(r.y) : "l"(v)); return r;
}

// ---------------------------------------------------------------------------
// Scratch (device globals: the sanctioned no-alloc workaround)
// ---------------------------------------------------------------------------
__device__ float    g_xh[(size_t)TT * NB * G4];   // (T, N, 4H) pre-projected gates, biases folded
__device__ unsigned g_bar[TT];                    // per-step grid barrier counters

// ---------------------------------------------------------------------------
// Kernel 1: xh = x @ W_xh + (b_xh + b_hh)   — FFMA2 inner loop (unchanged, R2)
// ---------------------------------------------------------------------------
#define BM 128
#define BN 128
#define BK 8

__global__ __launch_bounds__(256, 2)
void gemm_xh_kernel(const float* __restrict__ x,
                    const float* __restrict__ Wxh,
                    const float* __restrict__ bxh,
                    const float* __restrict__ bhh)
{
    __shared__ float As[BK][BM];   // transposed A tile
    __shared__ float Bs[BK][BN];

    const int tid = threadIdx.x;
    const int bm  = blockIdx.y;
    const int bn  = blockIdx.x;

    const int warp = tid >> 5, lane = tid & 31;
    const int wm = warp >> 1, wn = warp & 1;
    const int tm = lane & 3,  tn = lane >> 2;
    const int m0 = wm * 32 + tm * 8;
    const int n0 = wn * 64 + tn * 8;

    const int ar = tid >> 1;
    const int aq = tid & 1;
    const int gm = bm * BM + ar;            // global row m = t*64+n
    const int t  = gm >> 6;
    const int nn = gm & 63;
    const float* __restrict__ arow = x + ((size_t)nn * TT + t) * DD;

    const int rb = tid >> 5;
    const int cb = (tid & 31) * 4;
    const float* __restrict__ bcol = Wxh + (size_t)bn * BN + cb;

    u64 acc2[8][4];
#pragma unroll
    for (int i = 0; i < 8; i++)
#pragma unroll
        for (int j = 0; j < 4; j++) acc2[i][j] = 0ull;

    for (int k0 = 0; k0 < DD; k0 += BK) {
        const float4 av = *(const float4*)(arow + k0 + aq * 4);
        const float4 bv = *(const float4*)(bcol + (size_t)(k0 + rb) * G4);
        __syncthreads();
        As[aq * 4 + 0][ar] = av.x;
        As[aq * 4 + 1][ar] = av.y;
        As[aq * 4 + 2][ar] = av.z;
        As[aq * 4 + 3][ar] = av.w;
        *(float4*)&Bs[rb][cb] = bv;
        __syncthreads();

#pragma unroll
        for (int kk = 0; kk < BK; kk++) {
            float ra[8];
            *(float4*)&ra[0] = *(const float4*)&As[kk][m0];
            *(float4*)&ra[4] = *(const float4*)&As[kk][m0 + 4];
            const ulonglong2 b01 = *(const ulonglong2*)&Bs[kk][n0];
            const ulonglong2 b23 = *(const ulonglong2*)&Bs[kk][n0 + 4];
#pragma unroll
            for (int i = 0; i < 8; i++) {
                const u64 ai = pack_dup(ra[i]);
                ffma2(acc2[i][0], ai, b01.x);
                ffma2(acc2[i][1], ai, b01.y);
                ffma2(acc2[i][2], ai, b23.x);
                ffma2(acc2[i][3], ai, b23.y);
            }
        }
    }

    const int col0 = bn * BN + n0;
    float bsum[8];
#pragma unroll
    for (int j = 0; j < 8; j++)
        bsum[j] = bxh[col0 + j] + bhh[col0 + j];

#pragma unroll
    for (int i = 0; i < 8; i++) {
        const size_t row = (size_t)(bm * BM + m0 + i);
        float* p = g_xh + row * G4 + col0;
        float2 c0 = unpk(acc2[i][0]);
        float2 c1 = unpk(acc2[i][1]);
        float2 c2 = unpk(acc2[i][2]);
        float2 c3 = unpk(acc2[i][3]);
        float4 v0 = make_float4(c0.x + bsum[0], c0.y + bsum[1],
                                c1.x + bsum[2], c1.y + bsum[3]);
        float4 v1 = make_float4(c2.x + bsum[4], c2.y + bsum[5],
                                c3.x + bsum[6], c3.y + bsum[7]);
        *(float4*)p       = v0;
        *(float4*)(p + 4) = v1;
    }
}

// ---------------------------------------------------------------------------
// Kernel 2: barrier counter reset
// ---------------------------------------------------------------------------
__global__ void reset_bar_kernel()
{
    if (threadIdx.x < TT) g_bar[threadIdx.x] = 0u;
}

// ---------------------------------------------------------------------------
// Kernel 3: persistent LSTM recurrence.
// NEW: h(t-1) is staged into shared memory ONCE per step with fully
// coalesced row-major copies (nL=4 per LDG.128, 32-deep MLP), then the dot
// loop reads h via conflict-free broadcast LDS instead of 128 scattered
// LDG.128 (which had nL=8 -> ~8192 L1tex wavefronts/SM/step).
//   hs row stride = 516 floats (pad 4) -> 8 rows/warp hit distinct banks.
// Everything else as R2: smem-resident W_hh (k-contiguous, FFMA2 pairs),
// c state in registers, per-step release/acquire grid barrier.
// ---------------------------------------------------------------------------
#define NCTA 128
#define CPC  4            // hidden cols per CTA
#define WS_STRIDE 2052    // 4*512 + 4 floats per cg slice (bank-shift pad)
#define HS_STRIDE 516     // 512 + 4 floats per h row (bank-shift pad)
#define HS_BYTES  (NB * HS_STRIDE * 4)   // 132096

__device__ __forceinline__ float sigmoidf_(float v)
{
    return 1.f / (1.f + expf(-v));
}

__global__ __launch_bounds__(256, 1)
void lstm_kernel(const float* __restrict__ Whh, float* __restrict__ y)
{
    extern __shared__ float hs[];          // [NB][HS_STRIDE] staged h(t-1)
    __shared__ float wsT[4 * WS_STRIDE];   // ~32.8 KB
    __shared__ float gs[NB][17];           // gate staging, padded

    const int tid  = threadIdx.x;
    const int b    = blockIdx.x;
    const int jh0  = b * CPC;
    const int n    = tid >> 2;             // 0..63
    const int cg   = tid & 3;              // gate type: 0=i 1=f 2=g 3=o
    const int warp = tid >> 5;
    const int lane = tid & 31;

    // load + transpose W_hh slice into smem once
    for (int i = tid; i < 4 * 4 * HH; i += 256) {
        const int k = i & (HH - 1);
        const int j = (i >> 9) & 3;
        const int g = i >> 11;
        wsT[g * WS_STRIDE + j * HH + k] =
            Whh[(size_t)k * G4 + (size_t)g * HH + jh0 + j];
    }

    const float* __restrict__ wbase = &wsT[cg * WS_STRIDE];
    const float* __restrict__ hrow  = &hs[n * HS_STRIDE];

    const int n2 = tid >> 2;               // activation-phase mapping
    const int j2 = tid & 3;
    float creg = 0.f;                      // c state for (n2, jh0+j2)

    __syncthreads();

    for (int tstep = 0; tstep < TT; tstep++) {
        // ---- stage h(t-1) into smem, coalesced: warp w copies rows w, w+8, ...
        if (tstep > 0) {
            const size_t tb = (size_t)(tstep - 1) * HH;
#pragma unroll
            for (int r8 = 0; r8 < 8; r8++) {
                const int row = warp + r8 * 8;
                const float4* __restrict__ src =
                    (const float4*)(y + (size_t)row * TT * HH + tb);
                float4* __restrict__ dst = (float4*)&hs[row * HS_STRIDE];
#pragma unroll
                for (int p = 0; p < 4; p++)
                    dst[lane + p * 32] = src[lane + p * 32];
            }
        }
        __syncthreads();

        // ---- dot: gates for (n, cg, cols jh0..jh0+3) from smem h and smem W
        u64 acc0 = 0ull, acc1 = 0ull, acc2v = 0ull, acc3 = 0ull;
        if (tstep > 0) {
#pragma unroll 8
            for (int k = 0; k < HH; k += 4) {
                const ulonglong2 hp = *(const ulonglong2*)(hrow + k);
                const ulonglong2 w0 = *(const ulonglong2*)(wbase + 0 * HH + k);
                const ulonglong2 w1 = *(const ulonglong2*)(wbase + 1 * HH + k);
                const ulonglong2 w2 = *(const ulonglong2*)(wbase + 2 * HH + k);
                const ulonglong2 w3 = *(const ulonglong2*)(wbase + 3 * HH + k);
                ffma2(acc0, hp.x, w0.x); ffma2(acc0, hp.y, w0.y);
                ffma2(acc1, hp.x, w1.x); ffma2(acc1, hp.y, w1.y);
                ffma2(acc2v, hp.x, w2.x); ffma2(acc2v, hp.y, w2.y);
                ffma2(acc3, hp.x, w3.x); ffma2(acc3, hp.y, w3.y);
            }
        }

        // horizontal reduce + pre-projected input gates (biases folded in)
        float a0, a1, a2, a3;
        {
            const float2 s0 = unpk(acc0), s1 = unpk(acc1);
            const float2 s2 = unpk(acc2v), s3 = unpk(acc3);
            const float4 xv = *(const float4*)(g_xh +
                ((size_t)tstep * NB + n) * G4 + (size_t)cg * HH + jh0);
            a0 = s0.x + s0.y + xv.x;
            a1 = s1.x + s1.y + xv.y;
            a2 = s2.x + s2.y + xv.z;
            a3 = s3.x + s3.y + xv.w;
        }

        gs[n][cg * 4 + 0] = a0;
        gs[n][cg * 4 + 1] = a1;
        gs[n][cg * 4 + 2] = a2;
        gs[n][cg * 4 + 3] = a3;
        __syncthreads();

        // ---- activations: one output column per thread
        {
            const float gi = gs[n2][0  + j2];
            const float gf = gs[n2][4  + j2];
            const float gc = gs[n2][8  + j2];
            const float go = gs[n2][12 + j2];
            const float iv = sigmoidf_(gi);
            const float fv = sigmoidf_(gf);
            const float gv = tanhf(gc);
            const float ov = sigmoidf_(go);
            creg = fv * creg + iv * gv;
            const float hv = ov * tanhf(creg);
            y[(size_t)n2 * TT * HH + (size_t)tstep * HH + jh0 + j2] = hv;
        }
        __syncthreads();   // all y stores + gs reads done before barrier

        if (tstep < TT - 1) {
            // grid barrier (release/acquire, same pattern as CG grid.sync)
            if (tid == 0) {
                unsigned* ctr = &g_bar[tstep];
                asm volatile("red.release.gpu.add.u32 [%0], %1;"
                             :: "l"(ctr), "r"(1u) : "memory");
                unsigned v;
                do {
                    asm volatile("ld.acquire.gpu.u32 %0, [%1];"
                                 : "=r"(v) : "l"(ctr) : "memory");
                } while (v < (unsigned)NCTA);
            }
            __syncthreads();
        }
    }
}

// ---------------------------------------------------------------------------
// Launch
// ---------------------------------------------------------------------------
extern "C" void kernel_launch(void* const* d_in, const int* in_sizes, int n_in,
                              void* d_out, int out_size)
{
    const float* x   = (const float*)d_in[0];   // (64, 512, 512)
    const float* Wxh = (const float*)d_in[1];   // (512, 2048)
    const float* Whh = (const float*)d_in[2];   // (512, 2048)
    const float* bxh = (const float*)d_in[3];   // (2048,)
    const float* bhh = (const float*)d_in[4];   // (2048,)
    float* y = (float*)d_out;                   // (64, 512, 512)

    // opt-in to >48KB dynamic smem (idempotent host call, capture-safe)
    cudaFuncSetAttribute(lstm_kernel,
                         cudaFuncAttributeMaxDynamicSharedMemorySize, HS_BYTES);

    // barrier reset must precede the persistent kernel each call (graph replays)
    reset_bar_kernel<<<1, TT>>>();

    dim3 ggrid(G4 / BN, (TT * NB) / BM);        // (16, 256)
    gemm_xh_kernel<<<ggrid, 256>>>(x, Wxh, bxh, bhh);

    lstm_kernel<<<NCTA, 256, HS_BYTES>>>(Whh, y);
}